// round 15
// baseline (speedup 1.0000x reference)
#include <cuda_runtime.h>
#include <cuda.h>
#include <cuda_fp16.h>
#include <cstdint>

#define BATCH 16
#define T 1024
#define D 256
#define BM 128
#define BN 128
#define BK 64
#define NCH (D / BK)    // 4 chunks per tile
#define NSTG 3

// Scratch (allocation-free rule: __device__ globals). 1KB-aligned for TMA.
__device__ __align__(1024) __half g_xs[(size_t)BATCH * T * D];  // fp16(x * w3)
__device__ __align__(1024) __half g_yt[(size_t)BATCH * T * D];  // fp16(y)
__device__ float g_bias_x[BATCH * T];
__device__ float g_bias_y[BATCH * T];

__device__ __forceinline__ uint32_t smem_u32(const void* p) {
    uint32_t a;
    asm("{ .reg .u64 t; cvta.to.shared.u64 t, %1; cvt.u32.u64 %0, t; }" : "=r"(a) : "l"(p));
    return a;
}
__device__ __forceinline__ void ldsm_x4(uint32_t (&r)[4], uint32_t addr) {
    asm volatile("ldmatrix.sync.aligned.m8n8.x4.shared.b16 {%0,%1,%2,%3}, [%4];"
        : "=r"(r[0]), "=r"(r[1]), "=r"(r[2]), "=r"(r[3]) : "r"(addr));
}
__device__ __forceinline__ void mma_f16(float (&d)[4], const uint32_t (&a)[4],
                                        uint32_t b0, uint32_t b1) {
    asm volatile(
        "mma.sync.aligned.m16n8k16.row.col.f32.f16.f16.f32 "
        "{%0,%1,%2,%3}, {%4,%5,%6,%7}, {%8,%9}, {%0,%1,%2,%3};"
        : "+f"(d[0]), "+f"(d[1]), "+f"(d[2]), "+f"(d[3])
        : "r"(a[0]), "r"(a[1]), "r"(a[2]), "r"(a[3]), "r"(b0), "r"(b1));
}
#define MBARRIER_INIT(mbar, cnt) \
    asm volatile("mbarrier.init.shared.b64 [%0], %1;" :: "r"((uint32_t)(mbar)), "r"((uint32_t)(cnt)) : "memory")
#define MBARRIER_EXPECT_TX(mbar, bytes) \
    asm volatile("mbarrier.arrive.expect_tx.shared.b64 _, [%0], %1;" \
        :: "r"((uint32_t)(mbar)), "r"((uint32_t)(bytes)) : "memory")
#define MBARRIER_WAIT_PARITY(mbar, parity) do { \
    uint32_t _m = (uint32_t)(mbar), _p = (uint32_t)(parity), _d; \
    asm volatile("{ .reg .pred p; mbarrier.try_wait.parity.acquire.cta.shared::cta.b64 p, [%1], %2;" \
                 " selp.b32 %0,1,0,p; }" : "=r"(_d) : "r"(_m), "r"(_p) : "memory"); \
    if (!_d) { \
        asm volatile("{ .reg .pred P1; WL_%=:" \
            " mbarrier.try_wait.parity.acquire.cta.shared::cta.b64 P1, [%0], %1, 0x989680;" \
            " @P1 bra.uni WD_%=; bra.uni WL_%=; WD_%=: }" :: "r"(_m), "r"(_p) : "memory"); \
    } \
} while (0)
__device__ __forceinline__ void tma_load_2d(uint32_t dst, const void* map,
                                            int x, int y, uint32_t mbar) {
    asm volatile(
        "cp.async.bulk.tensor.2d.shared::cta.global.tile.mbarrier::complete_tx::bytes "
        "[%0], [%1, {%2, %3}], [%4];"
        :: "r"(dst), "l"(map), "r"(x), "r"(y), "r"(mbar) : "memory");
}

__device__ __forceinline__ uint32_t h2u(__half2 h) {
    uint32_t u;
    *(__half2*)&u = h;
    return u;
}

// ---------------- prep: 4 rows per warp, weights register-resident ----------------
// Each warp: load w1/w2/w3 slices ONCE (6 LDG), then 4 rows x (4 data LDG + packed stores).
__global__ void __launch_bounds__(256) prep_kernel(
    const float* __restrict__ x, const float* __restrict__ y, const float* __restrict__ WS) {
    const int warp = blockIdx.x * 8 + (threadIdx.x >> 5);
    const int lane = threadIdx.x & 31;
    const int row0 = warp * 4;

    const float4* w1 = (const float4*)WS;
    const float4* w2 = (const float4*)(WS + D);
    const float4* w3 = (const float4*)(WS + 2 * D);
    const float4 w1a = w1[lane], w1b = w1[lane + 32];
    const float4 w2a = w2[lane], w2b = w2[lane + 32];
    const float4 w3a = w3[lane], w3b = w3[lane + 32];

#pragma unroll
    for (int r = 0; r < 4; r++) {
        const int row = row0 + r;
        const float4* px = (const float4*)(x + (size_t)row * D);
        const float4* py = (const float4*)(y + (size_t)row * D);
        float4 xa = px[lane], xb = px[lane + 32];
        float4 ya = py[lane], yb = py[lane + 32];

        float sx = xa.x * w1a.x + xa.y * w1a.y + xa.z * w1a.z + xa.w * w1a.w
                 + xb.x * w1b.x + xb.y * w1b.y + xb.z * w1b.z + xb.w * w1b.w;
        float sy = ya.x * w2a.x + ya.y * w2a.y + ya.z * w2a.z + ya.w * w2a.w
                 + yb.x * w2b.x + yb.y * w2b.y + yb.z * w2b.z + yb.w * w2b.w;

        uint2 xsa, xsb, yta, ytb;
        xsa.x = h2u(__floats2half2_rn(xa.x * w3a.x, xa.y * w3a.y));
        xsa.y = h2u(__floats2half2_rn(xa.z * w3a.z, xa.w * w3a.w));
        xsb.x = h2u(__floats2half2_rn(xb.x * w3b.x, xb.y * w3b.y));
        xsb.y = h2u(__floats2half2_rn(xb.z * w3b.z, xb.w * w3b.w));
        yta.x = h2u(__floats2half2_rn(ya.x, ya.y));
        yta.y = h2u(__floats2half2_rn(ya.z, ya.w));
        ytb.x = h2u(__floats2half2_rn(yb.x, yb.y));
        ytb.y = h2u(__floats2half2_rn(yb.z, yb.w));

        uint2* xs8 = (uint2*)(g_xs + (size_t)row * D);
        uint2* yt8 = (uint2*)(g_yt + (size_t)row * D);
        xs8[lane] = xsa;
        xs8[lane + 32] = xsb;
        yt8[lane] = yta;
        yt8[lane + 32] = ytb;

#pragma unroll
        for (int o = 16; o; o >>= 1) {
            sx += __shfl_xor_sync(0xffffffffu, sx, o);
            sy += __shfl_xor_sync(0xffffffffu, sy, o);
        }
        if (lane == 0) {
            g_bias_x[row] = sx;
            g_bias_y[row] = sy;
        }
    }
}

// ---------------- TMA + mbarrier fp16 MMA GEMM (R14, unchanged) ----------------
#define ST_BYTES 32768
#define A_TILE 16384
#define OFF_MBAR (NSTG * ST_BYTES)          // 98304
#define SMEM_TMA (OFF_MBAR + 64)

__global__ void __launch_bounds__(256, 2) gemm_tma_kernel(
    float* __restrict__ out,
    const __grid_constant__ CUtensorMap mA,
    const __grid_constant__ CUtensorMap mB) {
    extern __shared__ char smc[];
    const uint32_t sbase = smem_u32(smc);

    const int tid = threadIdx.x;
    const int wid = tid >> 5, lane = tid & 31;
    const int b = blockIdx.z;
    const int tile_m = blockIdx.y * BM;
    const int tile_n = blockIdx.x * BN;
    const int rowA0 = b * T + tile_m;
    const int rowB0 = b * T + tile_n;

    // Warp layout: 2 (m) x 4 (n); warp tile 64 x 32
    const int warp_m = (wid >> 2) * 64;
    const int warp_n = (wid & 3) * 32;
    const int gid = lane >> 2;
    const int ctg = lane & 3;

    if (tid == 0) {
#pragma unroll
        for (int s = 0; s < NSTG; s++) MBARRIER_INIT(sbase + OFF_MBAR + s * 8, 1);
    }
    __syncthreads();

    auto issue = [&](int chunk) {
        int stg = chunk % NSTG;
        uint32_t mb = sbase + OFF_MBAR + stg * 8;
        MBARRIER_EXPECT_TX(mb, ST_BYTES);
        tma_load_2d(sbase + stg * ST_BYTES,          &mA, chunk * BK, rowA0, mb);
        tma_load_2d(sbase + stg * ST_BYTES + A_TILE, &mB, chunk * BK, rowB0, mb);
    };
    if (tid == 0) { issue(0); issue(1); }

    float acc[4][4][4];
#pragma unroll
    for (int i = 0; i < 4; i++)
#pragma unroll
        for (int j = 0; j < 4; j++)
#pragma unroll
            for (int r = 0; r < 4; r++) acc[i][j][r] = 0.f;

    // ldmatrix lane addressing within SW128-swizzled 128x64h tile (128B rows):
    // addr(row, unit16B) = row*128 + ((unit*16) ^ ((row&7)*16))
    const int rA = warp_m + (lane & 15);
    const uint32_t swzA = (uint32_t)(rA & 7) * 16;
    const uint32_t aoff0 = (uint32_t)rA * 128;
    const uint32_t aub = (uint32_t)(lane >> 4);
    const int rB = warp_n + (lane & 7) + ((lane >> 4) & 1) * 8;
    const uint32_t swzB = (uint32_t)(rB & 7) * 16;
    const uint32_t boff0 = (uint32_t)rB * 128;
    const uint32_t bub = (uint32_t)((lane >> 3) & 1);

#pragma unroll 1
    for (int c = 0; c < NCH; c++) {
        const int stg = c % NSTG;
        MBARRIER_WAIT_PARITY(sbase + OFF_MBAR + stg * 8, (c / NSTG) & 1);
        if (tid == 0 && c + 2 < NCH) issue(c + 2);

        const uint32_t abase = sbase + stg * ST_BYTES + aoff0;
        const uint32_t bbase = sbase + stg * ST_BYTES + A_TILE + boff0;
#pragma unroll
        for (int ks = 0; ks < 4; ks++) {
            uint32_t af[4][4], bq[2][4];
            const uint32_t aku = ((aub + ks * 2) * 16) ^ swzA;
            const uint32_t bku = ((bub + ks * 2) * 16) ^ swzB;
#pragma unroll
            for (int mf = 0; mf < 4; mf++)
                ldsm_x4(af[mf], abase + (uint32_t)mf * (16 * 128) + aku);
#pragma unroll
            for (int p = 0; p < 2; p++)
                ldsm_x4(bq[p], bbase + (uint32_t)p * (16 * 128) + bku);
#pragma unroll
            for (int mf = 0; mf < 4; mf++)
#pragma unroll
                for (int nf = 0; nf < 4; nf++)
                    mma_f16(acc[mf][nf], af[mf],
                            bq[nf >> 1][(nf & 1) * 2], bq[nf >> 1][(nf & 1) * 2 + 1]);
        }
        // Only stage 0 is ever rewritten (by issue(3) at c==1). The barrier after
        // chunk 0 is the full protection; barriers after chunks 1-2 protect nothing.
        if (c == 0) __syncthreads();
    }

    // Epilogue: + bias_x[row] + bias_y[col], float2 stores
    const float* bxp = g_bias_x + b * T + tile_m + warp_m;
    const float* byp = g_bias_y + b * T + tile_n + warp_n;
    float2 by[4];
#pragma unroll
    for (int nf = 0; nf < 4; nf++)
        by[nf] = *(const float2*)(byp + nf * 8 + ctg * 2);

#pragma unroll
    for (int mf = 0; mf < 4; mf++) {
        int r0 = warp_m + mf * 16 + gid;
        float bx0 = bxp[mf * 16 + gid];
        float bx1 = bxp[mf * 16 + gid + 8];
        float* C0 = out + ((size_t)b * T + tile_m + r0) * T + tile_n + warp_n;
        float* C1 = C0 + 8 * T;
#pragma unroll
        for (int nf = 0; nf < 4; nf++) {
            int coff = nf * 8 + ctg * 2;
            float2 v0 = make_float2(acc[mf][nf][0] + bx0 + by[nf].x,
                                    acc[mf][nf][1] + bx0 + by[nf].y);
            float2 v1 = make_float2(acc[mf][nf][2] + bx1 + by[nf].x,
                                    acc[mf][nf][3] + bx1 + by[nf].y);
            *(float2*)(C0 + coff) = v0;
            *(float2*)(C1 + coff) = v1;
        }
    }
}

typedef CUresult (*PFN_encodeTiled)(
    CUtensorMap*, CUtensorMapDataType, cuuint32_t, void*,
    const cuuint64_t*, const cuuint64_t*, const cuuint32_t*, const cuuint32_t*,
    CUtensorMapInterleave, CUtensorMapSwizzle, CUtensorMapL2promotion,
    CUtensorMapFloatOOBfill);

extern "C" void kernel_launch(void* const* d_in, const int* in_sizes, int n_in,
                              void* d_out, int out_size) {
    const float* x  = (const float*)d_in[0];
    const float* y  = (const float*)d_in[1];
    const float* WS = (const float*)d_in[2];
    float* out = (float*)d_out;

    // 4 rows per warp, 8 warps per block -> 32 rows per block
    prep_kernel<<<(BATCH * T) / 32, 256>>>(x, y, WS);

    void* fn = nullptr;
    cudaDriverEntryPointQueryResult qr = cudaDriverEntryPointSymbolNotFound;
    cudaGetDriverEntryPoint("cuTensorMapEncodeTiled", &fn, cudaEnableDefault, &qr);

    CUtensorMap mA, mB;
    void *xs_ptr = nullptr, *yt_ptr = nullptr;
    cudaGetSymbolAddress(&xs_ptr, g_xs);
    cudaGetSymbolAddress(&yt_ptr, g_yt);
    cuuint64_t dims[2]    = {(cuuint64_t)D, (cuuint64_t)(BATCH * T)};
    cuuint64_t strides[1] = {(cuuint64_t)(D * 2)};
    cuuint32_t box[2]     = {BK, BM};
    cuuint32_t estr[2]    = {1, 1};
    PFN_encodeTiled enc = (PFN_encodeTiled)fn;
    enc(&mA, CU_TENSOR_MAP_DATA_TYPE_UINT16, 2, xs_ptr, dims, strides,
        box, estr, CU_TENSOR_MAP_INTERLEAVE_NONE,
        CU_TENSOR_MAP_SWIZZLE_128B, CU_TENSOR_MAP_L2_PROMOTION_L2_128B,
        CU_TENSOR_MAP_FLOAT_OOB_FILL_NONE);
    enc(&mB, CU_TENSOR_MAP_DATA_TYPE_UINT16, 2, yt_ptr, dims, strides,
        box, estr, CU_TENSOR_MAP_INTERLEAVE_NONE,
        CU_TENSOR_MAP_SWIZZLE_128B, CU_TENSOR_MAP_L2_PROMOTION_L2_128B,
        CU_TENSOR_MAP_FLOAT_OOB_FILL_NONE);

    cudaFuncSetAttribute(gemm_tma_kernel, cudaFuncAttributeMaxDynamicSharedMemorySize, SMEM_TMA);
    dim3 grid(T / BN, T / BM, BATCH);   // (8, 8, 16) = 1024 CTAs
    gemm_tma_kernel<<<grid, 256, SMEM_TMA>>>(out, mA, mB);
}

// round 16
// speedup vs baseline: 1.0933x; 1.0933x over previous
#include <cuda_runtime.h>
#include <cuda.h>
#include <cuda_fp16.h>
#include <cstdint>

#define BATCH 16
#define T 1024
#define D 256
#define BM 128
#define BN 128
#define BK 64
#define NCH (D / BK)    // 4 chunks per tile
#define NSTG 3

// Scratch (allocation-free rule: __device__ globals). 1KB-aligned for TMA.
__device__ __align__(1024) __half g_xs[(size_t)BATCH * T * D];  // fp16(x * w3)
__device__ __align__(1024) __half g_yt[(size_t)BATCH * T * D];  // fp16(y)
__device__ float g_bias_x[BATCH * T];
__device__ float g_bias_y[BATCH * T];

__device__ __forceinline__ uint32_t smem_u32(const void* p) {
    uint32_t a;
    asm("{ .reg .u64 t; cvta.to.shared.u64 t, %1; cvt.u32.u64 %0, t; }" : "=r"(a) : "l"(p));
    return a;
}
__device__ __forceinline__ void ldsm_x4(uint32_t (&r)[4], uint32_t addr) {
    asm volatile("ldmatrix.sync.aligned.m8n8.x4.shared.b16 {%0,%1,%2,%3}, [%4];"
        : "=r"(r[0]), "=r"(r[1]), "=r"(r[2]), "=r"(r[3]) : "r"(addr));
}
__device__ __forceinline__ void mma_f16(float (&d)[4], const uint32_t (&a)[4],
                                        uint32_t b0, uint32_t b1) {
    asm volatile(
        "mma.sync.aligned.m16n8k16.row.col.f32.f16.f16.f32 "
        "{%0,%1,%2,%3}, {%4,%5,%6,%7}, {%8,%9}, {%0,%1,%2,%3};"
        : "+f"(d[0]), "+f"(d[1]), "+f"(d[2]), "+f"(d[3])
        : "r"(a[0]), "r"(a[1]), "r"(a[2]), "r"(a[3]), "r"(b0), "r"(b1));
}
#define MBARRIER_INIT(mbar, cnt) \
    asm volatile("mbarrier.init.shared.b64 [%0], %1;" :: "r"((uint32_t)(mbar)), "r"((uint32_t)(cnt)) : "memory")
#define MBARRIER_EXPECT_TX(mbar, bytes) \
    asm volatile("mbarrier.arrive.expect_tx.shared.b64 _, [%0], %1;" \
        :: "r"((uint32_t)(mbar)), "r"((uint32_t)(bytes)) : "memory")
#define MBARRIER_WAIT_PARITY(mbar, parity) do { \
    uint32_t _m = (uint32_t)(mbar), _p = (uint32_t)(parity), _d; \
    asm volatile("{ .reg .pred p; mbarrier.try_wait.parity.acquire.cta.shared::cta.b64 p, [%1], %2;" \
                 " selp.b32 %0,1,0,p; }" : "=r"(_d) : "r"(_m), "r"(_p) : "memory"); \
    if (!_d) { \
        asm volatile("{ .reg .pred P1; WL_%=:" \
            " mbarrier.try_wait.parity.acquire.cta.shared::cta.b64 P1, [%0], %1, 0x989680;" \
            " @P1 bra.uni WD_%=; bra.uni WL_%=; WD_%=: }" :: "r"(_m), "r"(_p) : "memory"); \
    } \
} while (0)
__device__ __forceinline__ void tma_load_2d(uint32_t dst, const void* map,
                                            int x, int y, uint32_t mbar) {
    asm volatile(
        "cp.async.bulk.tensor.2d.shared::cta.global.tile.mbarrier::complete_tx::bytes "
        "[%0], [%1, {%2, %3}], [%4];"
        :: "r"(dst), "l"(map), "r"(x), "r"(y), "r"(mbar) : "memory");
}

// ---------------- prep (R14 form): one warp handles x-row r AND y-row r ----------------
__global__ void __launch_bounds__(256) prep_kernel(
    const float* __restrict__ x, const float* __restrict__ y, const float* __restrict__ WS) {
    int row = blockIdx.x * 8 + (threadIdx.x >> 5);   // 0 .. BATCH*T-1
    int lane = threadIdx.x & 31;
    const float4* px = (const float4*)(x + (size_t)row * D);
    const float4* py = (const float4*)(y + (size_t)row * D);
    const float4* w1 = (const float4*)WS;
    const float4* w2 = (const float4*)(WS + D);
    const float4* w3 = (const float4*)(WS + 2 * D);
    __half2* xs2 = (__half2*)(g_xs + (size_t)row * D);
    __half2* yt2 = (__half2*)(g_yt + (size_t)row * D);

    float sx = 0.f, sy = 0.f;
#pragma unroll
    for (int i = 0; i < 2; i++) {
        int idx = lane + i * 32;
        float4 xv = px[idx], yv = py[idx];
        float4 a1 = w1[idx], a2 = w2[idx], a3 = w3[idx];
        sx += xv.x * a1.x + xv.y * a1.y + xv.z * a1.z + xv.w * a1.w;
        sy += yv.x * a2.x + yv.y * a2.y + yv.z * a2.z + yv.w * a2.w;
        xs2[idx * 2 + 0] = __floats2half2_rn(xv.x * a3.x, xv.y * a3.y);
        xs2[idx * 2 + 1] = __floats2half2_rn(xv.z * a3.z, xv.w * a3.w);
        yt2[idx * 2 + 0] = __floats2half2_rn(yv.x, yv.y);
        yt2[idx * 2 + 1] = __floats2half2_rn(yv.z, yv.w);
    }
#pragma unroll
    for (int o = 16; o; o >>= 1) {
        sx += __shfl_xor_sync(0xffffffffu, sx, o);
        sy += __shfl_xor_sync(0xffffffffu, sy, o);
    }
    if (lane == 0) {
        g_bias_x[row] = sx;
        g_bias_y[row] = sy;
    }
}

// ---------------- TMA + mbarrier fp16 MMA GEMM (R14 + smem bias staging) ----------------
#define ST_BYTES 32768
#define A_TILE 16384
#define OFF_MBAR (NSTG * ST_BYTES)          // 98304
#define OFF_BX (OFF_MBAR + 64)              // 128 floats
#define OFF_BY (OFF_BX + 512)               // 128 floats
#define SMEM_TMA (OFF_BY + 512)

__global__ void __launch_bounds__(256, 2) gemm_tma_kernel(
    float* __restrict__ out,
    const __grid_constant__ CUtensorMap mA,
    const __grid_constant__ CUtensorMap mB) {
    extern __shared__ char smc[];
    const uint32_t sbase = smem_u32(smc);

    const int tid = threadIdx.x;
    const int wid = tid >> 5, lane = tid & 31;
    const int b = blockIdx.z;
    const int tile_m = blockIdx.y * BM;
    const int tile_n = blockIdx.x * BN;
    const int rowA0 = b * T + tile_m;
    const int rowB0 = b * T + tile_n;

    // Warp layout: 2 (m) x 4 (n); warp tile 64 x 32
    const int warp_m = (wid >> 2) * 64;
    const int warp_n = (wid & 3) * 32;
    const int gid = lane >> 2;
    const int ctg = lane & 3;

    if (tid == 0) {
#pragma unroll
        for (int s = 0; s < NSTG; s++) MBARRIER_INIT(sbase + OFF_MBAR + s * 8, 1);
    }
    __syncthreads();

    auto issue = [&](int chunk) {
        int stg = chunk % NSTG;
        uint32_t mb = sbase + OFF_MBAR + stg * 8;
        MBARRIER_EXPECT_TX(mb, ST_BYTES);
        tma_load_2d(sbase + stg * ST_BYTES,          &mA, chunk * BK, rowA0, mb);
        tma_load_2d(sbase + stg * ST_BYTES + A_TILE, &mB, chunk * BK, rowB0, mb);
    };
    if (tid == 0) { issue(0); issue(1); }

    // Stage this tile's bias rows/cols into SMEM (hidden under the mainloop;
    // published to all warps by the c==0 __syncthreads below).
    if (tid < 128) {
        ((float*)(smc + OFF_BX))[tid] = g_bias_x[rowA0 + tid];
    } else {
        ((float*)(smc + OFF_BY))[tid - 128] = g_bias_y[rowB0 + tid - 128];
    }

    float acc[4][4][4];
#pragma unroll
    for (int i = 0; i < 4; i++)
#pragma unroll
        for (int j = 0; j < 4; j++)
#pragma unroll
            for (int r = 0; r < 4; r++) acc[i][j][r] = 0.f;

    // ldmatrix lane addressing within SW128-swizzled 128x64h tile (128B rows):
    // addr(row, unit16B) = row*128 + ((unit*16) ^ ((row&7)*16))
    const int rA = warp_m + (lane & 15);
    const uint32_t swzA = (uint32_t)(rA & 7) * 16;
    const uint32_t aoff0 = (uint32_t)rA * 128;
    const uint32_t aub = (uint32_t)(lane >> 4);
    const int rB = warp_n + (lane & 7) + ((lane >> 4) & 1) * 8;
    const uint32_t swzB = (uint32_t)(rB & 7) * 16;
    const uint32_t boff0 = (uint32_t)rB * 128;
    const uint32_t bub = (uint32_t)((lane >> 3) & 1);

#pragma unroll 1
    for (int c = 0; c < NCH; c++) {
        const int stg = c % NSTG;
        MBARRIER_WAIT_PARITY(sbase + OFF_MBAR + stg * 8, (c / NSTG) & 1);
        if (tid == 0 && c + 2 < NCH) issue(c + 2);

        const uint32_t abase = sbase + stg * ST_BYTES + aoff0;
        const uint32_t bbase = sbase + stg * ST_BYTES + A_TILE + boff0;
#pragma unroll
        for (int ks = 0; ks < 4; ks++) {
            uint32_t af[4][4], bq[2][4];
            const uint32_t aku = ((aub + ks * 2) * 16) ^ swzA;
            const uint32_t bku = ((bub + ks * 2) * 16) ^ swzB;
#pragma unroll
            for (int mf = 0; mf < 4; mf++)
                ldsm_x4(af[mf], abase + (uint32_t)mf * (16 * 128) + aku);
#pragma unroll
            for (int p = 0; p < 2; p++)
                ldsm_x4(bq[p], bbase + (uint32_t)p * (16 * 128) + bku);
#pragma unroll
            for (int mf = 0; mf < 4; mf++)
#pragma unroll
                for (int nf = 0; nf < 4; nf++)
                    mma_f16(acc[mf][nf], af[mf],
                            bq[nf >> 1][(nf & 1) * 2], bq[nf >> 1][(nf & 1) * 2 + 1]);
        }
        // Only stage 0 is ever rewritten (by issue(3) at c==1). This barrier also
        // publishes the SMEM bias staging to all warps.
        if (c == 0) __syncthreads();
    }

    // Epilogue: + bias_x[row] + bias_y[col] from SMEM (LDS, not LDG), float2 stores
    const float* bxs = (const float*)(smc + OFF_BX) + warp_m;
    const float* bys = (const float*)(smc + OFF_BY) + warp_n;
    float2 by[4];
#pragma unroll
    for (int nf = 0; nf < 4; nf++)
        by[nf] = *(const float2*)(bys + nf * 8 + ctg * 2);

#pragma unroll
    for (int mf = 0; mf < 4; mf++) {
        int r0 = warp_m + mf * 16 + gid;
        float bx0 = bxs[mf * 16 + gid];
        float bx1 = bxs[mf * 16 + gid + 8];
        float* C0 = out + ((size_t)b * T + tile_m + r0) * T + tile_n + warp_n;
        float* C1 = C0 + 8 * T;
#pragma unroll
        for (int nf = 0; nf < 4; nf++) {
            int coff = nf * 8 + ctg * 2;
            float2 v0 = make_float2(acc[mf][nf][0] + bx0 + by[nf].x,
                                    acc[mf][nf][1] + bx0 + by[nf].y);
            float2 v1 = make_float2(acc[mf][nf][2] + bx1 + by[nf].x,
                                    acc[mf][nf][3] + bx1 + by[nf].y);
            *(float2*)(C0 + coff) = v0;
            *(float2*)(C1 + coff) = v1;
        }
    }
}

typedef CUresult (*PFN_encodeTiled)(
    CUtensorMap*, CUtensorMapDataType, cuuint32_t, void*,
    const cuuint64_t*, const cuuint64_t*, const cuuint32_t*, const cuuint32_t*,
    CUtensorMapInterleave, CUtensorMapSwizzle, CUtensorMapL2promotion,
    CUtensorMapFloatOOBfill);

extern "C" void kernel_launch(void* const* d_in, const int* in_sizes, int n_in,
                              void* d_out, int out_size) {
    const float* x  = (const float*)d_in[0];
    const float* y  = (const float*)d_in[1];
    const float* WS = (const float*)d_in[2];
    float* out = (float*)d_out;

    prep_kernel<<<(BATCH * T) / 8, 256>>>(x, y, WS);

    void* fn = nullptr;
    cudaDriverEntryPointQueryResult qr = cudaDriverEntryPointSymbolNotFound;
    cudaGetDriverEntryPoint("cuTensorMapEncodeTiled", &fn, cudaEnableDefault, &qr);

    CUtensorMap mA, mB;
    void *xs_ptr = nullptr, *yt_ptr = nullptr;
    cudaGetSymbolAddress(&xs_ptr, g_xs);
    cudaGetSymbolAddress(&yt_ptr, g_yt);
    cuuint64_t dims[2]    = {(cuuint64_t)D, (cuuint64_t)(BATCH * T)};
    cuuint64_t strides[1] = {(cuuint64_t)(D * 2)};
    cuuint32_t box[2]     = {BK, BM};
    cuuint32_t estr[2]    = {1, 1};
    PFN_encodeTiled enc = (PFN_encodeTiled)fn;
    enc(&mA, CU_TENSOR_MAP_DATA_TYPE_UINT16, 2, xs_ptr, dims, strides,
        box, estr, CU_TENSOR_MAP_INTERLEAVE_NONE,
        CU_TENSOR_MAP_SWIZZLE_128B, CU_TENSOR_MAP_L2_PROMOTION_L2_128B,
        CU_TENSOR_MAP_FLOAT_OOB_FILL_NONE);
    enc(&mB, CU_TENSOR_MAP_DATA_TYPE_UINT16, 2, yt_ptr, dims, strides,
        box, estr, CU_TENSOR_MAP_INTERLEAVE_NONE,
        CU_TENSOR_MAP_SWIZZLE_128B, CU_TENSOR_MAP_L2_PROMOTION_L2_128B,
        CU_TENSOR_MAP_FLOAT_OOB_FILL_NONE);

    cudaFuncSetAttribute(gemm_tma_kernel, cudaFuncAttributeMaxDynamicSharedMemorySize, SMEM_TMA);
    dim3 grid(T / BN, T / BM, BATCH);   // (8, 8, 16) = 1024 CTAs
    gemm_tma_kernel<<<grid, 256, SMEM_TMA>>>(out, mA, mB);
}